// round 1
// baseline (speedup 1.0000x reference)
#include <cuda_runtime.h>

// Problem constants
#define BB 8
#define TT 2048
#define CC 1024

// Scratch (device globals — allocation-free per harness rules)
__device__ float g_xH[(size_t)BB * TT * CC];          // 64 MB : xH = x @ W^T
__device__ float g_sc[(size_t)BB * TT * TT];          // 128 MB: scores -> wei (in place)

// ---------------------------------------------------------------------------
// SGEMM  C = A * B^T   (A: [M,K] row-major, B: [N,K] row-major)
// 128x128 block tile, BK=8, 256 threads, 8x8 per-thread microtile.
// CAUSAL_SKIP: skip tiles fully above the strict-causal diagonal (bx > by).
// ---------------------------------------------------------------------------
template <bool CAUSAL_SKIP>
__global__ __launch_bounds__(256) void sgemm_nt(
    const float* __restrict__ A, const float* __restrict__ B, float* __restrict__ C,
    int M, int N, int K,
    long long strideA, long long strideB, long long strideC)
{
    const int bz = blockIdx.z;
    A += (long long)bz * strideA;
    B += (long long)bz * strideB;
    C += (long long)bz * strideC;

    const int by = blockIdx.y;   // M tile
    const int bx = blockIdx.x;   // N tile
    if (CAUSAL_SKIP && bx > by) return;   // tile entirely masked (s >= t for all)

    __shared__ float As[8][128];
    __shared__ float Bs[8][128];

    const int tid = threadIdx.x;          // 0..255
    const int tx  = tid & 15;             // N direction
    const int ty  = tid >> 4;             // M direction

    // Global load mapping: 128 rows x 8 K per tile, one float4 per thread.
    const int lrow = tid >> 1;            // 0..127
    const int lk4  = (tid & 1) * 4;       // 0 or 4

    const float* Ag = A + (long long)(by * 128 + lrow) * K + lk4;
    const float* Bg = B + (long long)(bx * 128 + lrow) * K + lk4;

    float acc[8][8] = {};
    float ra[8], rb[8];

    for (int k0 = 0; k0 < K; k0 += 8) {
        const float4 va = *(const float4*)(Ag + k0);
        const float4 vb = *(const float4*)(Bg + k0);
        __syncthreads();
        As[lk4 + 0][lrow] = va.x; As[lk4 + 1][lrow] = va.y;
        As[lk4 + 2][lrow] = va.z; As[lk4 + 3][lrow] = va.w;
        Bs[lk4 + 0][lrow] = vb.x; Bs[lk4 + 1][lrow] = vb.y;
        Bs[lk4 + 2][lrow] = vb.z; Bs[lk4 + 3][lrow] = vb.w;
        __syncthreads();
#pragma unroll
        for (int k = 0; k < 8; k++) {
#pragma unroll
            for (int i = 0; i < 8; i++) ra[i] = As[k][ty * 8 + i];
#pragma unroll
            for (int j = 0; j < 8; j++) rb[j] = Bs[k][tx * 8 + j];
#pragma unroll
            for (int i = 0; i < 8; i++)
#pragma unroll
                for (int j = 0; j < 8; j++)
                    acc[i][j] = fmaf(ra[i], rb[j], acc[i][j]);
        }
    }

#pragma unroll
    for (int i = 0; i < 8; i++) {
        const int row = by * 128 + ty * 8 + i;
        float4* cp = (float4*)(C + (long long)row * N + bx * 128 + tx * 8);
        cp[0] = make_float4(acc[i][0], acc[i][1], acc[i][2], acc[i][3]);
        cp[1] = make_float4(acc[i][4], acc[i][5], acc[i][6], acc[i][7]);
    }
}

// ---------------------------------------------------------------------------
// SGEMM  C = -(A * B)   (A: [M,K] row-major = wei, B: [K,N] row-major = xH)
// K-loop clamped to s < t0+128 (wei is zero at/after the diagonal).
// ---------------------------------------------------------------------------
__global__ __launch_bounds__(256) void sgemm_nn_neg(
    const float* __restrict__ Awei, const float* __restrict__ BxH, float* __restrict__ C,
    int M, int N, int Kfull)
{
    const int bz = blockIdx.z;
    const float* A = Awei + (long long)bz * M * Kfull;
    const float* B = BxH  + (long long)bz * Kfull * N;
    float* Cp      = C    + (long long)bz * M * N;

    const int by = blockIdx.y;
    const int bx = blockIdx.x;
    const int Klim = min(Kfull, (by + 1) * 128);  // only s < t0+128 contribute

    __shared__ float As[8][128];
    __shared__ float Bs[8][128];

    const int tid = threadIdx.x;
    const int tx  = tid & 15;
    const int ty  = tid >> 4;

    // A tile loader: 128 rows x 8 K
    const int larow = tid >> 1;
    const int lak4  = (tid & 1) * 4;
    const float* Ag = A + (long long)(by * 128 + larow) * Kfull + lak4;

    // B tile loader: 8 K-rows x 128 N
    const int lbk   = tid >> 5;            // 0..7
    const int lbn4  = (tid & 31) * 4;      // 0..124
    const float* Bg = B + (long long)lbk * N + bx * 128 + lbn4;

    float acc[8][8] = {};
    float ra[8], rb[8];

    for (int k0 = 0; k0 < Klim; k0 += 8) {
        const float4 va = *(const float4*)(Ag + k0);
        const float4 vb = *(const float4*)(Bg + (long long)k0 * N);
        __syncthreads();
        As[lak4 + 0][larow] = va.x; As[lak4 + 1][larow] = va.y;
        As[lak4 + 2][larow] = va.z; As[lak4 + 3][larow] = va.w;
        *(float4*)&Bs[lbk][lbn4] = vb;
        __syncthreads();
#pragma unroll
        for (int k = 0; k < 8; k++) {
#pragma unroll
            for (int i = 0; i < 8; i++) ra[i] = As[k][ty * 8 + i];
#pragma unroll
            for (int j = 0; j < 8; j++) rb[j] = Bs[k][tx * 8 + j];
#pragma unroll
            for (int i = 0; i < 8; i++)
#pragma unroll
                for (int j = 0; j < 8; j++)
                    acc[i][j] = fmaf(ra[i], rb[j], acc[i][j]);
        }
    }

#pragma unroll
    for (int i = 0; i < 8; i++) {
        const int row = by * 128 + ty * 8 + i;
        float4* cp = (float4*)(Cp + (long long)row * N + bx * 128 + tx * 8);
        cp[0] = make_float4(-acc[i][0], -acc[i][1], -acc[i][2], -acc[i][3]);
        cp[1] = make_float4(-acc[i][4], -acc[i][5], -acc[i][6], -acc[i][7]);
    }
}

// ---------------------------------------------------------------------------
// In-place strictly-causal softmax over each score row.
// Row t: softmax over s in [0, t); zeros for s >= t. Row 0 -> all zeros.
// One block (256 threads) per (b, t) row.
// ---------------------------------------------------------------------------
__global__ __launch_bounds__(256) void softmax_causal(float* __restrict__ sc)
{
    const long long row = blockIdx.x;          // b*T + t
    const int t = (int)(row % TT);
    float* p = sc + row * TT;
    const int tid = threadIdx.x;

    __shared__ float red[8];

    // ---- max over s < t ----
    float m = -3.0e38f;
    for (int s = tid; s < t; s += 256) m = fmaxf(m, p[s]);
#pragma unroll
    for (int o = 16; o; o >>= 1) m = fmaxf(m, __shfl_xor_sync(0xffffffffu, m, o));
    if ((tid & 31) == 0) red[tid >> 5] = m;
    __syncthreads();
    m = red[0];
#pragma unroll
    for (int w = 1; w < 8; w++) m = fmaxf(m, red[w]);
    __syncthreads();

    // ---- sum of exp ----
    float sum = 0.0f;
    for (int s = tid; s < t; s += 256) sum += expf(p[s] - m);
#pragma unroll
    for (int o = 16; o; o >>= 1) sum += __shfl_xor_sync(0xffffffffu, sum, o);
    if ((tid & 31) == 0) red[tid >> 5] = sum;
    __syncthreads();
    sum = red[0] + red[1] + red[2] + red[3] + red[4] + red[5] + red[6] + red[7];

    const float inv = (t > 0) ? (1.0f / sum) : 0.0f;

    // ---- write wei (zeros at/after the diagonal, covers row 0) ----
    for (int s = tid; s < TT; s += 256)
        p[s] = (s < t) ? expf(p[s] - m) * inv : 0.0f;
}

extern "C" void kernel_launch(void* const* d_in, const int* in_sizes, int n_in,
                              void* d_out, int out_size)
{
    const float* x = (const float*)d_in[0];   // [B,T,C]
    const float* W = (const float*)d_in[1];   // [C,C]  (out,in)
    float* out = (float*)d_out;               // [B,T,C]

    float* xH; cudaGetSymbolAddress((void**)&xH, g_xH);
    float* sc; cudaGetSymbolAddress((void**)&sc, g_sc);

    // K1: xH = x @ W^T, flattened over batch: [B*T, C] x [C, C]^T
    {
        dim3 grid(CC / 128, (BB * TT) / 128, 1);
        sgemm_nt<false><<<grid, 256>>>(x, W, xH, BB * TT, CC, CC, 0, 0, 0);
    }

    // K2: scores = x @ xH^T per batch, lower-triangular tiles only
    {
        dim3 grid(TT / 128, TT / 128, BB);
        sgemm_nt<true><<<grid, 256>>>(x, xH, sc, TT, TT, CC,
                                      (long long)TT * CC, (long long)TT * CC,
                                      (long long)TT * TT);
    }

    // K3: causal softmax in place (scores -> wei)
    softmax_causal<<<BB * TT, 256>>>(sc);

    // K4: out = -(wei @ xH) per batch, K clamped per row tile
    {
        dim3 grid(CC / 128, TT / 128, BB);
        sgemm_nn_neg<<<grid, 256>>>(sc, xH, out, TT, CC, TT);
    }
}

// round 3
// speedup vs baseline: 2.5522x; 2.5522x over previous
#include <cuda_runtime.h>
#include <cuda_bf16.h>
#include <cstdint>

#define BB 8
#define TT 2048
#define CC 1024

typedef __nv_bfloat16 bf16;

// Scratch (device globals — allocation-free)
__device__ bf16  g_xhi  [(size_t)BB * TT * CC];   // 32 MB
__device__ bf16  g_xlo  [(size_t)BB * TT * CC];   // 32 MB
__device__ bf16  g_whi  [(size_t)CC * CC];        // 2 MB
__device__ bf16  g_wlo  [(size_t)CC * CC];        // 2 MB
__device__ bf16  g_xHhi [(size_t)BB * TT * CC];   // 32 MB
__device__ bf16  g_xHlo [(size_t)BB * TT * CC];   // 32 MB
__device__ bf16  g_xHThi[(size_t)BB * TT * CC];   // 32 MB (xH^T, [C][T] per batch)
__device__ bf16  g_xHTlo[(size_t)BB * TT * CC];   // 32 MB
__device__ float g_sc   [(size_t)BB * TT * TT];   // 128 MB (fp32 scores)
__device__ bf16  g_weihi[(size_t)BB * TT * TT];   // 64 MB
__device__ bf16  g_weilo[(size_t)BB * TT * TT];   // 64 MB

// ===========================================================================
// helpers
// ===========================================================================
__device__ __forceinline__ uint32_t smem_u32(const void* p) {
    uint32_t a;
    asm("{ .reg .u64 t; cvta.to.shared.u64 t, %1; cvt.u32.u64 %0, t; }" : "=r"(a) : "l"(p));
    return a;
}
__device__ __forceinline__ void cp16(uint32_t s, const void* g) {
    asm volatile("cp.async.cg.shared.global [%0], [%1], 16;" :: "r"(s), "l"(g) : "memory");
}
__device__ __forceinline__ void ldsm4(uint32_t addr, uint32_t& r0, uint32_t& r1,
                                      uint32_t& r2, uint32_t& r3) {
    asm volatile("ldmatrix.sync.aligned.m8n8.x4.shared.b16 {%0,%1,%2,%3}, [%4];"
                 : "=r"(r0), "=r"(r1), "=r"(r2), "=r"(r3) : "r"(addr));
}
__device__ __forceinline__ void mma_bf16(float c[4], const uint32_t a[4], const uint32_t b[2]) {
    asm volatile(
        "mma.sync.aligned.m16n8k16.row.col.f32.bf16.bf16.f32 "
        "{%0,%1,%2,%3}, {%4,%5,%6,%7}, {%8,%9}, {%0,%1,%2,%3};"
        : "+f"(c[0]), "+f"(c[1]), "+f"(c[2]), "+f"(c[3])
        : "r"(a[0]), "r"(a[1]), "r"(a[2]), "r"(a[3]), "r"(b[0]), "r"(b[1]));
}

// ===========================================================================
// 3xBF16 GEMM:  C[M,N] (+opts) = A[M,K] @ B[N,K]^T with A,B given as bf16 hi/lo
// CTA 128x128, KC=32, 4-stage cp.async pipeline, ldmatrix fragments.
// OUTMODE: 0 = fp32, 1 = -fp32, 2 = bf16 hi/lo split pair
// ===========================================================================
#define AHI_OFF 0
#define ALO_OFF 10240
#define BHI_OFF 20480
#define BLO_OFF 30720
#define STG_BYTES 40960
#define NSTAGE 4
#define SMEM_TOTAL (NSTAGE * STG_BYTES)   // 163840

template <bool CAUSAL, bool KCLAMP, int OUTMODE>
__global__ __launch_bounds__(256, 1) void gemm_bf3(
    const bf16* __restrict__ Ahi, const bf16* __restrict__ Alo,
    const bf16* __restrict__ Bhi, const bf16* __restrict__ Blo,
    float* __restrict__ Cf, bf16* __restrict__ Chi, bf16* __restrict__ Clo,
    int lda, int ldb, int ldc, int Kfull,
    long long sA, long long sB, long long sC)
{
    const int bx = blockIdx.x, by = blockIdx.y, bz = blockIdx.z;
    if (CAUSAL && bx > by) return;     // tile fully masked (all s >= t)

    Ahi += (long long)bz * sA; Alo += (long long)bz * sA;
    Bhi += (long long)bz * sB; Blo += (long long)bz * sB;

    const int m0 = by * 128, n0 = bx * 128;
    const int Klim = KCLAMP ? min(Kfull, (by + 1) * 128) : Kfull;
    const int nc = Klim / 32;

    extern __shared__ char smem[];
    const uint32_t sbase = smem_u32(smem);
    const int tid = threadIdx.x;
    const int wid = tid >> 5, lane = tid & 31;
    const int wm = wid & 1, wn = wid >> 1;       // 2 x 4 warp grid
    const int g = lane >> 3, i = lane & 7;

    // ldmatrix per-lane offsets (80B padded rows)
    const uint32_t aLane = (uint32_t)((wm * 64 + i + (g & 1) * 8) * 80 + (g >> 1) * 16);
    const uint32_t bLane = (uint32_t)((wn * 32 + i + (g >> 1) * 8) * 80 + (g & 1) * 16);

    // loader mapping: 512 16B ops per region, 2 reps of 256
    const int  l_row = tid >> 2;
    const int  l_seg = (tid & 3) * 8;                   // bf16 elems (8 = 16B)
    const uint32_t l_soff = (uint32_t)((tid >> 2) * 80 + (tid & 3) * 16);

    float acc[4][4][4];
#pragma unroll
    for (int a = 0; a < 4; a++)
#pragma unroll
        for (int b = 0; b < 4; b++)
#pragma unroll
            for (int c = 0; c < 4; c++) acc[a][b][c] = 0.f;

    auto issue = [&](int ch) {
        const uint32_t st = sbase + (uint32_t)(ch & 3) * STG_BYTES;
        const long long k0 = (long long)ch * 32;
#pragma unroll
        for (int rep = 0; rep < 2; rep++) {
            const int row = l_row + rep * 64;
            const uint32_t so = l_soff + rep * 64 * 80;
            cp16(st + AHI_OFF + so, Ahi + (long long)(m0 + row) * lda + k0 + l_seg);
            cp16(st + ALO_OFF + so, Alo + (long long)(m0 + row) * lda + k0 + l_seg);
            cp16(st + BHI_OFF + so, Bhi + (long long)(n0 + row) * ldb + k0 + l_seg);
            cp16(st + BLO_OFF + so, Blo + (long long)(n0 + row) * ldb + k0 + l_seg);
        }
    };

#pragma unroll
    for (int s = 0; s < NSTAGE - 1; s++) {
        if (s < nc) issue(s);
        asm volatile("cp.async.commit_group;" ::: "memory");
    }

    for (int ch = 0; ch < nc; ch++) {
        asm volatile("cp.async.wait_group %0;" :: "n"(NSTAGE - 2) : "memory");
        __syncthreads();
        if (ch + NSTAGE - 1 < nc) issue(ch + NSTAGE - 1);
        asm volatile("cp.async.commit_group;" ::: "memory");

        const uint32_t st = sbase + (uint32_t)(ch & 3) * STG_BYTES;
        const uint32_t aHi = st + AHI_OFF + aLane;
        const uint32_t aLo = st + ALO_OFF + aLane;
        const uint32_t bHi = st + BHI_OFF + bLane;
        const uint32_t bLo = st + BLO_OFF + bLane;

#pragma unroll
        for (int ks = 0; ks < 2; ks++) {
            uint32_t ah[4][4], al[4][4], bh[4][2], bl[4][2];
#pragma unroll
            for (int mt = 0; mt < 4; mt++) {
                ldsm4(aHi + mt * (16 * 80) + ks * 32, ah[mt][0], ah[mt][1], ah[mt][2], ah[mt][3]);
                ldsm4(aLo + mt * (16 * 80) + ks * 32, al[mt][0], al[mt][1], al[mt][2], al[mt][3]);
            }
#pragma unroll
            for (int j = 0; j < 2; j++) {
                uint32_t r0, r1, r2, r3;
                ldsm4(bHi + j * (16 * 80) + ks * 32, r0, r1, r2, r3);
                bh[2 * j][0] = r0; bh[2 * j][1] = r1; bh[2 * j + 1][0] = r2; bh[2 * j + 1][1] = r3;
                ldsm4(bLo + j * (16 * 80) + ks * 32, r0, r1, r2, r3);
                bl[2 * j][0] = r0; bl[2 * j][1] = r1; bl[2 * j + 1][0] = r2; bl[2 * j + 1][1] = r3;
            }
#pragma unroll
            for (int mt = 0; mt < 4; mt++)
#pragma unroll
                for (int nt = 0; nt < 4; nt++) mma_bf16(acc[mt][nt], ah[mt], bh[nt]);
#pragma unroll
            for (int mt = 0; mt < 4; mt++)
#pragma unroll
                for (int nt = 0; nt < 4; nt++) mma_bf16(acc[mt][nt], ah[mt], bl[nt]);
#pragma unroll
            for (int mt = 0; mt < 4; mt++)
#pragma unroll
                for (int nt = 0; nt < 4; nt++) mma_bf16(acc[mt][nt], al[mt], bh[nt]);
        }
    }

    // ---- epilogue (direct register -> global) ----
    const int rr = lane >> 2, cb = (lane & 3) * 2;
#pragma unroll
    for (int mt = 0; mt < 4; mt++) {
#pragma unroll
        for (int nt = 0; nt < 4; nt++) {
            const int row = m0 + wm * 64 + mt * 16 + rr;
            const int col = n0 + wn * 32 + nt * 8 + cb;
            float s0 = acc[mt][nt][0], s1 = acc[mt][nt][1];
            float s2 = acc[mt][nt][2], s3 = acc[mt][nt][3];
            if (OUTMODE == 0 || OUTMODE == 1) {
                if (OUTMODE == 1) { s0 = -s0; s1 = -s1; s2 = -s2; s3 = -s3; }
                float* base = Cf + (long long)bz * sC;
                *(float2*)(base + (long long)row * ldc + col)       = make_float2(s0, s1);
                *(float2*)(base + (long long)(row + 8) * ldc + col) = make_float2(s2, s3);
            } else {
                bf16* oh = Chi + (long long)bz * sC;
                bf16* ol = Clo + (long long)bz * sC;
                bf16 h0 = __float2bfloat16(s0), h1 = __float2bfloat16(s1);
                bf16 h2 = __float2bfloat16(s2), h3 = __float2bfloat16(s3);
                bf16 l0 = __float2bfloat16(s0 - __bfloat162float(h0));
                bf16 l1 = __float2bfloat16(s1 - __bfloat162float(h1));
                bf16 l2 = __float2bfloat16(s2 - __bfloat162float(h2));
                bf16 l3 = __float2bfloat16(s3 - __bfloat162float(h3));
                *(__nv_bfloat162*)(oh + (long long)row * ldc + col)       = __halves2bfloat162(h0, h1);
                *(__nv_bfloat162*)(oh + (long long)(row + 8) * ldc + col) = __halves2bfloat162(h2, h3);
                *(__nv_bfloat162*)(ol + (long long)row * ldc + col)       = __halves2bfloat162(l0, l1);
                *(__nv_bfloat162*)(ol + (long long)(row + 8) * ldc + col) = __halves2bfloat162(l2, l3);
            }
        }
    }
}

// ===========================================================================
// fp32 -> bf16 hi/lo split
// ===========================================================================
__global__ __launch_bounds__(256) void split_bf16(
    const float* __restrict__ src, bf16* __restrict__ hi, bf16* __restrict__ lo, long long n)
{
    for (long long idx = (long long)blockIdx.x * 256 + threadIdx.x; idx < n;
         idx += (long long)gridDim.x * 256) {
        const float x = src[idx];
        const bf16 h = __float2bfloat16(x);
        hi[idx] = h;
        lo[idx] = __float2bfloat16(x - __bfloat162float(h));
    }
}

// ===========================================================================
// Batched transpose of bf16 hi/lo pair: out[b][c][t] = in[b][t][c]
// ===========================================================================
__global__ __launch_bounds__(256) void transpose_pair(
    const bf16* __restrict__ ih, const bf16* __restrict__ il,
    bf16* __restrict__ oh, bf16* __restrict__ ol)
{
    __shared__ bf16 th[32][33], tl[32][33];
    const int b = blockIdx.z;
    const int t0 = blockIdx.x * 32, c0 = blockIdx.y * 32;
    ih += (size_t)b * TT * CC; il += (size_t)b * TT * CC;
    oh += (size_t)b * TT * CC; ol += (size_t)b * TT * CC;
    const int x = threadIdx.x, y = threadIdx.y;   // 32 x 8
#pragma unroll
    for (int j = 0; j < 32; j += 8) {
        th[y + j][x] = ih[(size_t)(t0 + y + j) * CC + c0 + x];
        tl[y + j][x] = il[(size_t)(t0 + y + j) * CC + c0 + x];
    }
    __syncthreads();
#pragma unroll
    for (int j = 0; j < 32; j += 8) {
        oh[(size_t)(c0 + y + j) * TT + t0 + x] = th[x][y + j];
        ol[(size_t)(c0 + y + j) * TT + t0 + x] = tl[x][y + j];
    }
}

// ===========================================================================
// Causal softmax: fp32 scores row -> bf16 hi/lo wei row (zeros at/after diag)
// ===========================================================================
__global__ __launch_bounds__(256) void softmax_causal(
    const float* __restrict__ sc, bf16* __restrict__ whi, bf16* __restrict__ wlo)
{
    const long long row = blockIdx.x;          // b*T + t
    const int t = (int)(row % TT);
    const float* p = sc + row * TT;
    bf16* oh = whi + row * TT;
    bf16* ol = wlo + row * TT;
    const int tid = threadIdx.x;

    __shared__ float red[8];

    float m = -3.0e38f;
    for (int s = tid; s < t; s += 256) m = fmaxf(m, p[s]);
#pragma unroll
    for (int o = 16; o; o >>= 1) m = fmaxf(m, __shfl_xor_sync(0xffffffffu, m, o));
    if ((tid & 31) == 0) red[tid >> 5] = m;
    __syncthreads();
    m = red[0];
#pragma unroll
    for (int w = 1; w < 8; w++) m = fmaxf(m, red[w]);
    __syncthreads();

    float sum = 0.0f;
    for (int s = tid; s < t; s += 256) sum += expf(p[s] - m);
#pragma unroll
    for (int o = 16; o; o >>= 1) sum += __shfl_xor_sync(0xffffffffu, sum, o);
    if ((tid & 31) == 0) red[tid >> 5] = sum;
    __syncthreads();
    sum = red[0] + red[1] + red[2] + red[3] + red[4] + red[5] + red[6] + red[7];

    const float inv = (t > 0) ? (1.0f / sum) : 0.0f;

    for (int s = tid; s < TT; s += 256) {
        const float w = (s < t) ? expf(p[s] - m) * inv : 0.0f;
        const bf16 h = __float2bfloat16(w);
        oh[s] = h;
        ol[s] = __float2bfloat16(w - __bfloat162float(h));
    }
}

// ===========================================================================
extern "C" void kernel_launch(void* const* d_in, const int* in_sizes, int n_in,
                              void* d_out, int out_size)
{
    const float* x = (const float*)d_in[0];   // [B,T,C]
    const float* W = (const float*)d_in[1];   // [C,C]
    float* out = (float*)d_out;               // [B,T,C]

    bf16 *xhi, *xlo, *whi, *wlo, *xHhi, *xHlo, *xHThi, *xHTlo, *weihi, *weilo;
    float* sc;
    cudaGetSymbolAddress((void**)&xhi,   g_xhi);
    cudaGetSymbolAddress((void**)&xlo,   g_xlo);
    cudaGetSymbolAddress((void**)&whi,   g_whi);
    cudaGetSymbolAddress((void**)&wlo,   g_wlo);
    cudaGetSymbolAddress((void**)&xHhi,  g_xHhi);
    cudaGetSymbolAddress((void**)&xHlo,  g_xHlo);
    cudaGetSymbolAddress((void**)&xHThi, g_xHThi);
    cudaGetSymbolAddress((void**)&xHTlo, g_xHTlo);
    cudaGetSymbolAddress((void**)&weihi, g_weihi);
    cudaGetSymbolAddress((void**)&weilo, g_weilo);
    cudaGetSymbolAddress((void**)&sc,    g_sc);

    cudaFuncSetAttribute(gemm_bf3<false, false, 2>,
                         cudaFuncAttributeMaxDynamicSharedMemorySize, SMEM_TOTAL);
    cudaFuncSetAttribute(gemm_bf3<true, false, 0>,
                         cudaFuncAttributeMaxDynamicSharedMemorySize, SMEM_TOTAL);
    cudaFuncSetAttribute(gemm_bf3<false, true, 1>,
                         cudaFuncAttributeMaxDynamicSharedMemorySize, SMEM_TOTAL);

    // split inputs to bf16 hi/lo
    split_bf16<<<8192, 256>>>(x, xhi, xlo, (long long)BB * TT * CC);
    split_bf16<<<2048, 256>>>(W, whi, wlo, (long long)CC * CC);

    // K1: xH = x @ W^T  -> bf16 hi/lo   [B*T, C] x [C, C]^T
    gemm_bf3<false, false, 2><<<dim3(CC / 128, (BB * TT) / 128, 1), 256, SMEM_TOTAL>>>(
        xhi, xlo, whi, wlo, nullptr, xHhi, xHlo,
        CC, CC, CC, CC, 0, 0, 0);

    // transpose xH -> xHT ([C][T] per batch), hi and lo
    transpose_pair<<<dim3(TT / 32, CC / 32, BB), dim3(32, 8)>>>(xHhi, xHlo, xHThi, xHTlo);

    // K2: scores(fp32) = x @ xH^T per batch, causal tiles only
    gemm_bf3<true, false, 0><<<dim3(TT / 128, TT / 128, BB), 256, SMEM_TOTAL>>>(
        xhi, xlo, xHhi, xHlo, sc, nullptr, nullptr,
        CC, CC, TT, CC,
        (long long)TT * CC, (long long)TT * CC, (long long)TT * TT);

    // K3: causal softmax -> wei bf16 hi/lo
    softmax_causal<<<BB * TT, 256>>>(sc, weihi, weilo);

    // K4: out = -(wei @ xHT^T) per batch, K clamped per row tile
    gemm_bf3<false, true, 1><<<dim3(CC / 128, TT / 128, BB), 256, SMEM_TOTAL>>>(
        weihi, weilo, xHThi, xHTlo, out, nullptr, nullptr,
        TT, TT, CC, TT,
        (long long)TT * TT, (long long)TT * CC, (long long)TT * CC);
}

// round 4
// speedup vs baseline: 2.8793x; 1.1282x over previous
#include <cuda_runtime.h>
#include <cuda_bf16.h>
#include <cstdint>

#define BB 8
#define TT 2048
#define CC 1024

typedef __nv_bfloat16 bf16;

// Scratch (device globals — allocation-free)
__device__ bf16   g_xhi  [(size_t)BB * TT * CC];   // 32 MB
__device__ bf16   g_xlo  [(size_t)BB * TT * CC];   // 32 MB
__device__ bf16   g_whi  [(size_t)CC * CC];        // 2 MB
__device__ bf16   g_wlo  [(size_t)CC * CC];        // 2 MB
__device__ bf16   g_xHhi [(size_t)BB * TT * CC];   // 32 MB
__device__ bf16   g_xHlo [(size_t)BB * TT * CC];   // 32 MB
__device__ float  g_sc   [(size_t)BB * TT * TT];   // 128 MB (fp32 scores)
__device__ float2 g_stats[(size_t)BB * TT];        // per-row (max, 1/sumexp)

// ===========================================================================
// helpers
// ===========================================================================
__device__ __forceinline__ uint32_t smem_u32(const void* p) {
    uint32_t a;
    asm("{ .reg .u64 t; cvta.to.shared.u64 t, %1; cvt.u32.u64 %0, t; }" : "=r"(a) : "l"(p));
    return a;
}
__device__ __forceinline__ void cp16(uint32_t s, const void* g) {
    asm volatile("cp.async.cg.shared.global [%0], [%1], 16;" :: "r"(s), "l"(g) : "memory");
}
__device__ __forceinline__ void ldsm4(uint32_t addr, uint32_t& r0, uint32_t& r1,
                                      uint32_t& r2, uint32_t& r3) {
    asm volatile("ldmatrix.sync.aligned.m8n8.x4.shared.b16 {%0,%1,%2,%3}, [%4];"
                 : "=r"(r0), "=r"(r1), "=r"(r2), "=r"(r3) : "r"(addr));
}
__device__ __forceinline__ void ldsm4t(uint32_t addr, uint32_t& r0, uint32_t& r1,
                                       uint32_t& r2, uint32_t& r3) {
    asm volatile("ldmatrix.sync.aligned.m8n8.x4.trans.shared.b16 {%0,%1,%2,%3}, [%4];"
                 : "=r"(r0), "=r"(r1), "=r"(r2), "=r"(r3) : "r"(addr));
}
__device__ __forceinline__ void mma_bf16(float c[4], const uint32_t a[4], const uint32_t b[2]) {
    asm volatile(
        "mma.sync.aligned.m16n8k16.row.col.f32.bf16.bf16.f32 "
        "{%0,%1,%2,%3}, {%4,%5,%6,%7}, {%8,%9}, {%0,%1,%2,%3};"
        : "+f"(c[0]), "+f"(c[1]), "+f"(c[2]), "+f"(c[3])
        : "r"(a[0]), "r"(a[1]), "r"(a[2]), "r"(a[3]), "r"(b[0]), "r"(b[1]));
}

// ===========================================================================
// 3xBF16 GEMM:  C = A[M,K] @ B[N,K]^T,  A/B bf16 hi/lo, 128x128 tile, KC=32
// 2-stage cp.async pipeline, 2 CTAs/SM.
// OUTMODE: 0 = fp32, 2 = bf16 hi/lo split pair
// ===========================================================================
#define AHI_OFF 0
#define ALO_OFF 10240
#define BHI_OFF 20480
#define BLO_OFF 30720
#define STG_BYTES 40960
#define SMEM_TOTAL (2 * STG_BYTES)   // 81920

template <bool CAUSAL, int OUTMODE>
__global__ __launch_bounds__(256, 2) void gemm_bf3(
    const bf16* __restrict__ Ahi, const bf16* __restrict__ Alo,
    const bf16* __restrict__ Bhi, const bf16* __restrict__ Blo,
    float* __restrict__ Cf, bf16* __restrict__ Chi, bf16* __restrict__ Clo,
    int lda, int ldb, int ldc, int Kfull,
    long long sA, long long sB, long long sC)
{
    const int bx = blockIdx.x, by = blockIdx.y, bz = blockIdx.z;
    if (CAUSAL && bx > by) return;     // tile fully masked (all s >= t)

    Ahi += (long long)bz * sA; Alo += (long long)bz * sA;
    Bhi += (long long)bz * sB; Blo += (long long)bz * sB;

    const int m0 = by * 128, n0 = bx * 128;
    const int nc = Kfull / 32;

    extern __shared__ char smem[];
    const uint32_t sbase = smem_u32(smem);
    const int tid = threadIdx.x;
    const int wid = tid >> 5, lane = tid & 31;
    const int wm = wid & 1, wn = wid >> 1;       // 2 x 4 warp grid (64x32 tiles)
    const int g = lane >> 3, i = lane & 7;

    const uint32_t aLane = (uint32_t)((wm * 64 + i + (g & 1) * 8) * 80 + (g >> 1) * 16);
    const uint32_t bLane = (uint32_t)((wn * 32 + i + (g >> 1) * 8) * 80 + (g & 1) * 16);

    const int  l_row = tid >> 2;
    const int  l_seg = (tid & 3) * 8;
    const uint32_t l_soff = (uint32_t)((tid >> 2) * 80 + (tid & 3) * 16);

    float acc[4][4][4];
#pragma unroll
    for (int a = 0; a < 4; a++)
#pragma unroll
        for (int b = 0; b < 4; b++)
#pragma unroll
            for (int c = 0; c < 4; c++) acc[a][b][c] = 0.f;

    auto issue = [&](int ch) {
        const uint32_t st = sbase + (uint32_t)(ch & 1) * STG_BYTES;
        const long long k0 = (long long)ch * 32;
#pragma unroll
        for (int rep = 0; rep < 2; rep++) {
            const int row = l_row + rep * 64;
            const uint32_t so = l_soff + rep * 64 * 80;
            cp16(st + AHI_OFF + so, Ahi + (long long)(m0 + row) * lda + k0 + l_seg);
            cp16(st + ALO_OFF + so, Alo + (long long)(m0 + row) * lda + k0 + l_seg);
            cp16(st + BHI_OFF + so, Bhi + (long long)(n0 + row) * ldb + k0 + l_seg);
            cp16(st + BLO_OFF + so, Blo + (long long)(n0 + row) * ldb + k0 + l_seg);
        }
    };

    issue(0);
    asm volatile("cp.async.commit_group;" ::: "memory");

    for (int ch = 0; ch < nc; ch++) {
        asm volatile("cp.async.wait_group 0;" ::: "memory");
        __syncthreads();
        if (ch + 1 < nc) issue(ch + 1);
        asm volatile("cp.async.commit_group;" ::: "memory");

        const uint32_t st = sbase + (uint32_t)(ch & 1) * STG_BYTES;
        const uint32_t aHi = st + AHI_OFF + aLane;
        const uint32_t aLo = st + ALO_OFF + aLane;
        const uint32_t bHi = st + BHI_OFF + bLane;
        const uint32_t bLo = st + BLO_OFF + bLane;

#pragma unroll
        for (int ks = 0; ks < 2; ks++) {
            uint32_t ah[4][4], al[4][4], bh[4][2], bl[4][2];
#pragma unroll
            for (int mt = 0; mt < 4; mt++) {
                ldsm4(aHi + mt * (16 * 80) + ks * 32, ah[mt][0], ah[mt][1], ah[mt][2], ah[mt][3]);
                ldsm4(aLo + mt * (16 * 80) + ks * 32, al[mt][0], al[mt][1], al[mt][2], al[mt][3]);
            }
#pragma unroll
            for (int j = 0; j < 2; j++) {
                uint32_t r0, r1, r2, r3;
                ldsm4(bHi + j * (16 * 80) + ks * 32, r0, r1, r2, r3);
                bh[2 * j][0] = r0; bh[2 * j][1] = r1; bh[2 * j + 1][0] = r2; bh[2 * j + 1][1] = r3;
                ldsm4(bLo + j * (16 * 80) + ks * 32, r0, r1, r2, r3);
                bl[2 * j][0] = r0; bl[2 * j][1] = r1; bl[2 * j + 1][0] = r2; bl[2 * j + 1][1] = r3;
            }
#pragma unroll
            for (int mt = 0; mt < 4; mt++)
#pragma unroll
                for (int nt = 0; nt < 4; nt++) mma_bf16(acc[mt][nt], ah[mt], bh[nt]);
#pragma unroll
            for (int mt = 0; mt < 4; mt++)
#pragma unroll
                for (int nt = 0; nt < 4; nt++) mma_bf16(acc[mt][nt], ah[mt], bl[nt]);
#pragma unroll
            for (int mt = 0; mt < 4; mt++)
#pragma unroll
                for (int nt = 0; nt < 4; nt++) mma_bf16(acc[mt][nt], al[mt], bh[nt]);
        }
    }

    // ---- epilogue ----
    const int rr = lane >> 2, cb = (lane & 3) * 2;
#pragma unroll
    for (int mt = 0; mt < 4; mt++) {
#pragma unroll
        for (int nt = 0; nt < 4; nt++) {
            const int row = m0 + wm * 64 + mt * 16 + rr;
            const int col = n0 + wn * 32 + nt * 8 + cb;
            const float s0 = acc[mt][nt][0], s1 = acc[mt][nt][1];
            const float s2 = acc[mt][nt][2], s3 = acc[mt][nt][3];
            if (OUTMODE == 0) {
                float* base = Cf + (long long)bz * sC;
                *(float2*)(base + (long long)row * ldc + col)       = make_float2(s0, s1);
                *(float2*)(base + (long long)(row + 8) * ldc + col) = make_float2(s2, s3);
            } else {
                bf16* oh = Chi + (long long)bz * sC;
                bf16* ol = Clo + (long long)bz * sC;
                bf16 h0 = __float2bfloat16(s0), h1 = __float2bfloat16(s1);
                bf16 h2 = __float2bfloat16(s2), h3 = __float2bfloat16(s3);
                bf16 l0 = __float2bfloat16(s0 - __bfloat162float(h0));
                bf16 l1 = __float2bfloat16(s1 - __bfloat162float(h1));
                bf16 l2 = __float2bfloat16(s2 - __bfloat162float(h2));
                bf16 l3 = __float2bfloat16(s3 - __bfloat162float(h3));
                *(__nv_bfloat162*)(oh + (long long)row * ldc + col)       = __halves2bfloat162(h0, h1);
                *(__nv_bfloat162*)(oh + (long long)(row + 8) * ldc + col) = __halves2bfloat162(h2, h3);
                *(__nv_bfloat162*)(ol + (long long)row * ldc + col)       = __halves2bfloat162(l0, l1);
                *(__nv_bfloat162*)(ol + (long long)(row + 8) * ldc + col) = __halves2bfloat162(l2, l3);
            }
        }
    }
}

// ===========================================================================
// K4: out[t][c] = -sum_s wei[t][s] * xH[s][c]
// wei computed on the fly from fp32 scores + row stats; B via ldmatrix.trans.
// ===========================================================================
#define W_AHI 0
#define W_ALO 10240
#define W_BHI 20480
#define W_BLO 29184
#define W_STG 37888
#define W_SMEM (4 * W_STG)   // 151552

__global__ __launch_bounds__(256, 1) void gemm_wei(
    const float* __restrict__ scA, const float2* __restrict__ stats,
    const bf16* __restrict__ Bhi, const bf16* __restrict__ Blo,
    float* __restrict__ Out)
{
    const int bx = blockIdx.x, by = blockIdx.y, bz = blockIdx.z;
    const float* sc = scA + (long long)bz * TT * TT;
    const float2* stt = stats + (long long)bz * TT;
    const bf16* bhi = Bhi + (long long)bz * TT * CC;
    const bf16* blo = Blo + (long long)bz * TT * CC;
    float* out = Out + (long long)bz * TT * CC;

    const int m0 = by * 128, n0 = bx * 128;
    const int Klim = min(TT, (by + 1) * 128);
    const int nc = Klim / 32;

    extern __shared__ char smem[];
    const uint32_t sbase = smem_u32(smem);
    const int tid = threadIdx.x;
    const int wid = tid >> 5, lane = tid & 31;
    const int wm = wid & 1, wn = wid >> 1;
    const int g = lane >> 3, i = lane & 7;

    const uint32_t aLane = (uint32_t)((wm * 64 + i + (g & 1) * 8) * 80 + (g >> 1) * 16);
    // B trans lane: row = lane&15, col-block = (lane>>4)*16B
    const uint32_t bLaneT = (uint32_t)((lane & 15) * 272 + (lane >> 4) * 16 + wn * 64);

    // A (wei) loader: row = tid>>1 (t), half = tid&1 (16 s-cols)
    const int arow = tid >> 1, aseg = tid & 1;
    const int t_glob = m0 + arow;
    const float2 rs = stt[t_glob];      // (max, inv)
    float4 pa[4];

    auto ldgA = [&](int ch) {
        const float* src = sc + (long long)t_glob * TT + ch * 32 + aseg * 16;
        pa[0] = *(const float4*)(src + 0);
        pa[1] = *(const float4*)(src + 4);
        pa[2] = *(const float4*)(src + 8);
        pa[3] = *(const float4*)(src + 12);
    };
    auto stsA = [&](int ch) {
        char* stg = smem + (size_t)(ch & 3) * W_STG;
        const int sb0 = ch * 32 + aseg * 16;
        uint32_t hi[8], lo[8];
#pragma unroll
        for (int q = 0; q < 4; q++) {
            const float vv[4] = { pa[q].x, pa[q].y, pa[q].z, pa[q].w };
            float w[4];
#pragma unroll
            for (int e = 0; e < 4; e++) {
                const int s = sb0 + q * 4 + e;
                w[e] = (s < t_glob) ? __expf(vv[e] - rs.x) * rs.y : 0.0f;
            }
#pragma unroll
            for (int e = 0; e < 4; e += 2) {
                const bf16 h0 = __float2bfloat16(w[e]);
                const bf16 h1 = __float2bfloat16(w[e + 1]);
                const bf16 l0 = __float2bfloat16(w[e] - __bfloat162float(h0));
                const bf16 l1 = __float2bfloat16(w[e + 1] - __bfloat162float(h1));
                __nv_bfloat162 ph = __halves2bfloat162(h0, h1);
                __nv_bfloat162 pl = __halves2bfloat162(l0, l1);
                hi[q * 2 + e / 2] = *(uint32_t*)&ph;
                lo[q * 2 + e / 2] = *(uint32_t*)&pl;
            }
        }
        const size_t off = (size_t)arow * 80 + (size_t)aseg * 32;
        *(uint4*)(stg + W_AHI + off)      = *(uint4*)(hi + 0);
        *(uint4*)(stg + W_AHI + off + 16) = *(uint4*)(hi + 4);
        *(uint4*)(stg + W_ALO + off)      = *(uint4*)(lo + 0);
        *(uint4*)(stg + W_ALO + off + 16) = *(uint4*)(lo + 4);
    };
    auto issueB = [&](int ch) {
        const uint32_t st = sbase + (uint32_t)(ch & 3) * W_STG;
        const long long k0 = (long long)ch * 32;
#pragma unroll
        for (int r = 0; r < 2; r++) {
            const int idx = tid + r * 256;
            const int brow = idx >> 4, bseg = idx & 15;
            const long long go = (k0 + brow) * CC + n0 + bseg * 8;
            const uint32_t so = (uint32_t)(brow * 272 + bseg * 16);
            cp16(st + W_BHI + so, bhi + go);
            cp16(st + W_BLO + so, blo + go);
        }
    };

    float acc[4][4][4];
#pragma unroll
    for (int a = 0; a < 4; a++)
#pragma unroll
        for (int b = 0; b < 4; b++)
#pragma unroll
            for (int c = 0; c < 4; c++) acc[a][b][c] = 0.f;

    ldgA(0);
#pragma unroll
    for (int s = 0; s < 3; s++) {
        if (s < nc) issueB(s);
        asm volatile("cp.async.commit_group;" ::: "memory");
    }

    for (int ch = 0; ch < nc; ch++) {
        asm volatile("cp.async.wait_group 2;" ::: "memory");
        stsA(ch);
        __syncthreads();
        if (ch + 1 < nc) ldgA(ch + 1);
        if (ch + 3 < nc) issueB(ch + 3);
        asm volatile("cp.async.commit_group;" ::: "memory");

        const uint32_t st = sbase + (uint32_t)(ch & 3) * W_STG;
        const uint32_t aHi = st + W_AHI + aLane;
        const uint32_t aLo = st + W_ALO + aLane;
        const uint32_t bHi = st + W_BHI + bLaneT;
        const uint32_t bLo = st + W_BLO + bLaneT;

#pragma unroll
        for (int ks = 0; ks < 2; ks++) {
            uint32_t ah[4][4], al[4][4], bh[4][2], bl[4][2];
#pragma unroll
            for (int mt = 0; mt < 4; mt++) {
                ldsm4(aHi + mt * (16 * 80) + ks * 32, ah[mt][0], ah[mt][1], ah[mt][2], ah[mt][3]);
                ldsm4(aLo + mt * (16 * 80) + ks * 32, al[mt][0], al[mt][1], al[mt][2], al[mt][3]);
            }
#pragma unroll
            for (int j = 0; j < 2; j++) {
                uint32_t r0, r1, r2, r3;
                ldsm4t(bHi + ks * (16 * 272) + j * 32, r0, r1, r2, r3);
                bh[2 * j][0] = r0; bh[2 * j][1] = r1; bh[2 * j + 1][0] = r2; bh[2 * j + 1][1] = r3;
                ldsm4t(bLo + ks * (16 * 272) + j * 32, r0, r1, r2, r3);
                bl[2 * j][0] = r0; bl[2 * j][1] = r1; bl[2 * j + 1][0] = r2; bl[2 * j + 1][1] = r3;
            }
#pragma unroll
            for (int mt = 0; mt < 4; mt++)
#pragma unroll
                for (int nt = 0; nt < 4; nt++) mma_bf16(acc[mt][nt], ah[mt], bh[nt]);
#pragma unroll
            for (int mt = 0; mt < 4; mt++)
#pragma unroll
                for (int nt = 0; nt < 4; nt++) mma_bf16(acc[mt][nt], ah[mt], bl[nt]);
#pragma unroll
            for (int mt = 0; mt < 4; mt++)
#pragma unroll
                for (int nt = 0; nt < 4; nt++) mma_bf16(acc[mt][nt], al[mt], bh[nt]);
        }
    }

    const int rr = lane >> 2, cb = (lane & 3) * 2;
#pragma unroll
    for (int mt = 0; mt < 4; mt++) {
#pragma unroll
        for (int nt = 0; nt < 4; nt++) {
            const int row = m0 + wm * 64 + mt * 16 + rr;
            const int col = n0 + wn * 32 + nt * 8 + cb;
            *(float2*)(out + (long long)row * CC + col) =
                make_float2(-acc[mt][nt][0], -acc[mt][nt][1]);
            *(float2*)(out + (long long)(row + 8) * CC + col) =
                make_float2(-acc[mt][nt][2], -acc[mt][nt][3]);
        }
    }
}

// ===========================================================================
// fp32 -> bf16 hi/lo split
// ===========================================================================
__global__ __launch_bounds__(256) void split_bf16(
    const float* __restrict__ src, bf16* __restrict__ hi, bf16* __restrict__ lo, long long n)
{
    for (long long idx = (long long)blockIdx.x * 256 + threadIdx.x; idx < n;
         idx += (long long)gridDim.x * 256) {
        const float x = src[idx];
        const bf16 h = __float2bfloat16(x);
        hi[idx] = h;
        lo[idx] = __float2bfloat16(x - __bfloat162float(h));
    }
}

// ===========================================================================
// Row stats: m = max_{s<t} score, inv = 1/sum exp(score-m); (0-row -> inv=0)
// ===========================================================================
__global__ __launch_bounds__(256) void row_stats(
    const float* __restrict__ sc, float2* __restrict__ stats)
{
    const long long row = blockIdx.x;          // b*T + t
    const int t = (int)(row % TT);
    const float* p = sc + row * TT;
    const int tid = threadIdx.x;

    __shared__ float red[8];

    float m = -3.0e38f;
    for (int s = tid; s < t; s += 256) m = fmaxf(m, p[s]);
#pragma unroll
    for (int o = 16; o; o >>= 1) m = fmaxf(m, __shfl_xor_sync(0xffffffffu, m, o));
    if ((tid & 31) == 0) red[tid >> 5] = m;
    __syncthreads();
    m = red[0];
#pragma unroll
    for (int w = 1; w < 8; w++) m = fmaxf(m, red[w]);
    __syncthreads();

    float sum = 0.0f;
    for (int s = tid; s < t; s += 256) sum += __expf(p[s] - m);
#pragma unroll
    for (int o = 16; o; o >>= 1) sum += __shfl_xor_sync(0xffffffffu, sum, o);
    if ((tid & 31) == 0) red[tid >> 5] = sum;
    __syncthreads();

    if (tid == 0) {
        sum = red[0] + red[1] + red[2] + red[3] + red[4] + red[5] + red[6] + red[7];
        stats[row] = make_float2(m, (t > 0) ? (1.0f / sum) : 0.0f);
    }
}

// ===========================================================================
extern "C" void kernel_launch(void* const* d_in, const int* in_sizes, int n_in,
                              void* d_out, int out_size)
{
    const float* x = (const float*)d_in[0];   // [B,T,C]
    const float* W = (const float*)d_in[1];   // [C,C]
    float* out = (float*)d_out;               // [B,T,C]

    bf16 *xhi, *xlo, *whi, *wlo, *xHhi, *xHlo;
    float* sc; float2* stats;
    cudaGetSymbolAddress((void**)&xhi,   g_xhi);
    cudaGetSymbolAddress((void**)&xlo,   g_xlo);
    cudaGetSymbolAddress((void**)&whi,   g_whi);
    cudaGetSymbolAddress((void**)&wlo,   g_wlo);
    cudaGetSymbolAddress((void**)&xHhi,  g_xHhi);
    cudaGetSymbolAddress((void**)&xHlo,  g_xHlo);
    cudaGetSymbolAddress((void**)&sc,    g_sc);
    cudaGetSymbolAddress((void**)&stats, g_stats);

    cudaFuncSetAttribute(gemm_bf3<false, 2>,
                         cudaFuncAttributeMaxDynamicSharedMemorySize, SMEM_TOTAL);
    cudaFuncSetAttribute(gemm_bf3<true, 0>,
                         cudaFuncAttributeMaxDynamicSharedMemorySize, SMEM_TOTAL);
    cudaFuncSetAttribute(gemm_wei,
                         cudaFuncAttributeMaxDynamicSharedMemorySize, W_SMEM);

    // split inputs to bf16 hi/lo
    split_bf16<<<8192, 256>>>(x, xhi, xlo, (long long)BB * TT * CC);
    split_bf16<<<2048, 256>>>(W, whi, wlo, (long long)CC * CC);

    // K1: xH = x @ W^T  -> bf16 hi/lo
    gemm_bf3<false, 2><<<dim3(CC / 128, (BB * TT) / 128, 1), 256, SMEM_TOTAL>>>(
        xhi, xlo, whi, wlo, nullptr, xHhi, xHlo,
        CC, CC, CC, CC, 0, 0, 0);

    // K2: scores(fp32) = x @ xH^T per batch, causal tiles only
    gemm_bf3<true, 0><<<dim3(TT / 128, TT / 128, BB), 256, SMEM_TOTAL>>>(
        xhi, xlo, xHhi, xHlo, sc, nullptr, nullptr,
        CC, CC, TT, CC,
        (long long)TT * CC, (long long)TT * CC, (long long)TT * TT);

    // K3: row stats (max, 1/sumexp)
    row_stats<<<BB * TT, 256>>>(sc, stats);

    // K4: out = -(wei @ xH), wei from scores on the fly, K clamped
    gemm_wei<<<dim3(CC / 128, TT / 128, BB), 256, W_SMEM>>>(
        sc, stats, xHhi, xHlo, out);
}

// round 5
// speedup vs baseline: 2.9935x; 1.0396x over previous
#include <cuda_runtime.h>
#include <cuda_bf16.h>
#include <cstdint>

#define BB 8
#define TT 2048
#define CC 1024

typedef __nv_bfloat16 bf16;

// Scratch (device globals — allocation-free)
__device__ bf16   g_xhi  [(size_t)BB * TT * CC];   // 32 MB
__device__ bf16   g_xlo  [(size_t)BB * TT * CC];   // 32 MB
__device__ bf16   g_whi  [(size_t)CC * CC];        // 2 MB
__device__ bf16   g_wlo  [(size_t)CC * CC];        // 2 MB
__device__ bf16   g_xHhi [(size_t)BB * TT * CC];   // 32 MB
__device__ bf16   g_xHlo [(size_t)BB * TT * CC];   // 32 MB
__device__ float  g_sc   [(size_t)BB * TT * TT];   // 128 MB (fp32 scores)
__device__ float2 g_stats[(size_t)BB * TT];        // per-row (max, 1/sumexp)

// ===========================================================================
// helpers
// ===========================================================================
__device__ __forceinline__ uint32_t smem_u32(const void* p) {
    uint32_t a;
    asm("{ .reg .u64 t; cvta.to.shared.u64 t, %1; cvt.u32.u64 %0, t; }" : "=r"(a) : "l"(p));
    return a;
}
__device__ __forceinline__ void cp16(uint32_t s, const void* g) {
    asm volatile("cp.async.cg.shared.global [%0], [%1], 16;" :: "r"(s), "l"(g) : "memory");
}
__device__ __forceinline__ void ldsm4(uint32_t addr, uint32_t& r0, uint32_t& r1,
                                      uint32_t& r2, uint32_t& r3) {
    asm volatile("ldmatrix.sync.aligned.m8n8.x4.shared.b16 {%0,%1,%2,%3}, [%4];"
                 : "=r"(r0), "=r"(r1), "=r"(r2), "=r"(r3) : "r"(addr));
}
__device__ __forceinline__ void ldsm4t(uint32_t addr, uint32_t& r0, uint32_t& r1,
                                       uint32_t& r2, uint32_t& r3) {
    asm volatile("ldmatrix.sync.aligned.m8n8.x4.trans.shared.b16 {%0,%1,%2,%3}, [%4];"
                 : "=r"(r0), "=r"(r1), "=r"(r2), "=r"(r3) : "r"(addr));
}
__device__ __forceinline__ void mma_bf16(float c[4], const uint32_t a[4], const uint32_t b[2]) {
    asm volatile(
        "mma.sync.aligned.m16n8k16.row.col.f32.bf16.bf16.f32 "
        "{%0,%1,%2,%3}, {%4,%5,%6,%7}, {%8,%9}, {%0,%1,%2,%3};"
        : "+f"(c[0]), "+f"(c[1]), "+f"(c[2]), "+f"(c[3])
        : "r"(a[0]), "r"(a[1]), "r"(a[2]), "r"(a[3]), "r"(b[0]), "r"(b[1]));
}

// swizzled 16B-chunk offset within a 128x32-bf16 (64B-row) K-major tile
__device__ __forceinline__ uint32_t swz(int row, int chunk) {
    return (uint32_t)(row * 64 + ((chunk ^ ((row >> 1) & 3)) << 4));
}

// ===========================================================================
// 3xBF16 GEMM:  C = A[M,K] @ B[N,K]^T, bf16 hi/lo inputs, 128x128 tile, KC=32
// 3-stage cp.async pipeline, swizzled 64B rows, 2 CTAs/SM.
// OUTMODE: 0 = fp32, 2 = bf16 hi/lo split pair
// ===========================================================================
#define AHI_OFF 0
#define ALO_OFF 8192
#define BHI_OFF 16384
#define BLO_OFF 24576
#define STG_BYTES 32768
#define SMEM_TOTAL (3 * STG_BYTES)   // 98304

template <bool CAUSAL, int OUTMODE>
__global__ __launch_bounds__(256, 2) void gemm_bf3(
    const bf16* __restrict__ Ahi, const bf16* __restrict__ Alo,
    const bf16* __restrict__ Bhi, const bf16* __restrict__ Blo,
    float* __restrict__ Cf, bf16* __restrict__ Chi, bf16* __restrict__ Clo,
    int lda, int ldb, int ldc, int Kfull,
    long long sA, long long sB, long long sC)
{
    const int bx = blockIdx.x, by = blockIdx.y, bz = blockIdx.z;
    if (CAUSAL && bx > by) return;

    Ahi += (long long)bz * sA; Alo += (long long)bz * sA;
    Bhi += (long long)bz * sB; Blo += (long long)bz * sB;

    const int m0 = by * 128, n0 = bx * 128;
    const int nc = Kfull / 32;

    extern __shared__ char smem[];
    const uint32_t sbase = smem_u32(smem);
    const int tid = threadIdx.x;
    const int wid = tid >> 5, lane = tid & 31;
    const int wm = wid & 1, wn = wid >> 1;
    const int g = lane >> 3, i = lane & 7;

    // fragment lane geometry
    const int arow_base = wm * 64 + i + (g & 1) * 8;    // + mt*16
    const int brow_base = wn * 32 + i + (g >> 1) * 8;   // + j*16
    const int achunk0 = g >> 1;                          // + ks*2
    const int bchunk0 = g & 1;                           // + ks*2

    // loader: idx -> row (0..127), chunk (0..3)
    const int l_row = tid >> 2, l_ch = tid & 3;
    const uint32_t l_soff0 = swz(l_row, l_ch);
    const uint32_t l_soff1 = swz(l_row + 64, l_ch);

    float acc[4][4][4];
#pragma unroll
    for (int a = 0; a < 4; a++)
#pragma unroll
        for (int b = 0; b < 4; b++)
#pragma unroll
            for (int c = 0; c < 4; c++) acc[a][b][c] = 0.f;

    auto issue = [&](int ch) {
        const uint32_t st = sbase + (uint32_t)(ch % 3) * STG_BYTES;
        const long long k0 = (long long)ch * 32 + l_ch * 8;
        {
            const long long ga = (long long)(m0 + l_row) * lda + k0;
            const long long gb = (long long)(n0 + l_row) * ldb + k0;
            cp16(st + AHI_OFF + l_soff0, Ahi + ga);
            cp16(st + ALO_OFF + l_soff0, Alo + ga);
            cp16(st + BHI_OFF + l_soff0, Bhi + gb);
            cp16(st + BLO_OFF + l_soff0, Blo + gb);
        }
        {
            const long long ga = (long long)(m0 + l_row + 64) * lda + k0;
            const long long gb = (long long)(n0 + l_row + 64) * ldb + k0;
            cp16(st + AHI_OFF + l_soff1, Ahi + ga);
            cp16(st + ALO_OFF + l_soff1, Alo + ga);
            cp16(st + BHI_OFF + l_soff1, Bhi + gb);
            cp16(st + BLO_OFF + l_soff1, Blo + gb);
        }
    };

#pragma unroll
    for (int s = 0; s < 2; s++) {
        if (s < nc) issue(s);
        asm volatile("cp.async.commit_group;" ::: "memory");
    }

    for (int ch = 0; ch < nc; ch++) {
        asm volatile("cp.async.wait_group 1;" ::: "memory");
        __syncthreads();
        if (ch + 2 < nc) issue(ch + 2);
        asm volatile("cp.async.commit_group;" ::: "memory");

        const uint32_t st = sbase + (uint32_t)(ch % 3) * STG_BYTES;

#pragma unroll
        for (int ks = 0; ks < 2; ks++) {
            uint32_t ah[4][4], al[4][4], bh[4][2], bl[4][2];
#pragma unroll
            for (int mt = 0; mt < 4; mt++) {
                const uint32_t ao = swz(arow_base + mt * 16, achunk0 + ks * 2);
                ldsm4(st + AHI_OFF + ao, ah[mt][0], ah[mt][1], ah[mt][2], ah[mt][3]);
                ldsm4(st + ALO_OFF + ao, al[mt][0], al[mt][1], al[mt][2], al[mt][3]);
            }
#pragma unroll
            for (int j = 0; j < 2; j++) {
                const uint32_t bo = swz(brow_base + j * 16, bchunk0 + ks * 2);
                uint32_t r0, r1, r2, r3;
                ldsm4(st + BHI_OFF + bo, r0, r1, r2, r3);
                bh[2 * j][0] = r0; bh[2 * j][1] = r1; bh[2 * j + 1][0] = r2; bh[2 * j + 1][1] = r3;
                ldsm4(st + BLO_OFF + bo, r0, r1, r2, r3);
                bl[2 * j][0] = r0; bl[2 * j][1] = r1; bl[2 * j + 1][0] = r2; bl[2 * j + 1][1] = r3;
            }
#pragma unroll
            for (int mt = 0; mt < 4; mt++)
#pragma unroll
                for (int nt = 0; nt < 4; nt++) mma_bf16(acc[mt][nt], ah[mt], bh[nt]);
#pragma unroll
            for (int mt = 0; mt < 4; mt++)
#pragma unroll
                for (int nt = 0; nt < 4; nt++) mma_bf16(acc[mt][nt], ah[mt], bl[nt]);
#pragma unroll
            for (int mt = 0; mt < 4; mt++)
#pragma unroll
                for (int nt = 0; nt < 4; nt++) mma_bf16(acc[mt][nt], al[mt], bh[nt]);
        }
    }

    // ---- epilogue ----
    const int rr = lane >> 2, cb = (lane & 3) * 2;
#pragma unroll
    for (int mt = 0; mt < 4; mt++) {
#pragma unroll
        for (int nt = 0; nt < 4; nt++) {
            const int row = m0 + wm * 64 + mt * 16 + rr;
            const int col = n0 + wn * 32 + nt * 8 + cb;
            const float s0 = acc[mt][nt][0], s1 = acc[mt][nt][1];
            const float s2 = acc[mt][nt][2], s3 = acc[mt][nt][3];
            if (OUTMODE == 0) {
                float* base = Cf + (long long)bz * sC;
                *(float2*)(base + (long long)row * ldc + col)       = make_float2(s0, s1);
                *(float2*)(base + (long long)(row + 8) * ldc + col) = make_float2(s2, s3);
            } else {
                bf16* oh = Chi + (long long)bz * sC;
                bf16* ol = Clo + (long long)bz * sC;
                bf16 h0 = __float2bfloat16(s0), h1 = __float2bfloat16(s1);
                bf16 h2 = __float2bfloat16(s2), h3 = __float2bfloat16(s3);
                bf16 l0 = __float2bfloat16(s0 - __bfloat162float(h0));
                bf16 l1 = __float2bfloat16(s1 - __bfloat162float(h1));
                bf16 l2 = __float2bfloat16(s2 - __bfloat162float(h2));
                bf16 l3 = __float2bfloat16(s3 - __bfloat162float(h3));
                *(__nv_bfloat162*)(oh + (long long)row * ldc + col)       = __halves2bfloat162(h0, h1);
                *(__nv_bfloat162*)(oh + (long long)(row + 8) * ldc + col) = __halves2bfloat162(h2, h3);
                *(__nv_bfloat162*)(ol + (long long)row * ldc + col)       = __halves2bfloat162(l0, l1);
                *(__nv_bfloat162*)(ol + (long long)(row + 8) * ldc + col) = __halves2bfloat162(l2, l3);
            }
        }
    }
}

// ===========================================================================
// K4: out[t][c] = -sum_s wei[t][s] * xH[s][c]
// wei from fp32 scores + row stats on the fly; 3 stages, 2 CTA/SM.
// ===========================================================================
#define W_AHI 0
#define W_ALO 8192
#define W_BHI 16384
#define W_BLO 25088
#define W_STG 33792
#define W_SMEM (3 * W_STG)   // 101376

__global__ __launch_bounds__(256, 2) void gemm_wei(
    const float* __restrict__ scA, const float2* __restrict__ stats,
    const bf16* __restrict__ Bhi, const bf16* __restrict__ Blo,
    float* __restrict__ Out)
{
    const int bx = blockIdx.x, by = blockIdx.y, bz = blockIdx.z;
    const float* sc = scA + (long long)bz * TT * TT;
    const float2* stt = stats + (long long)bz * TT;
    const bf16* bhi = Bhi + (long long)bz * TT * CC;
    const bf16* blo = Blo + (long long)bz * TT * CC;
    float* out = Out + (long long)bz * TT * CC;

    const int m0 = by * 128, n0 = bx * 128;
    const int Klim = min(TT, (by + 1) * 128);
    const int nc = Klim / 32;

    extern __shared__ char smem[];
    const uint32_t sbase = smem_u32(smem);
    const int tid = threadIdx.x;
    const int wid = tid >> 5, lane = tid & 31;
    const int wm = wid & 1, wn = wid >> 1;
    const int g = lane >> 3, i = lane & 7;

    const int arow_base = wm * 64 + i + (g & 1) * 8;
    const int achunk0 = g >> 1;
    const uint32_t bLaneT = (uint32_t)((lane & 15) * 272 + (lane >> 4) * 16 + wn * 64);

    // A (wei) producer: row = tid>>1 (t), seg = tid&1 (16 s-cols = chunks 2seg,2seg+1)
    const int arow = tid >> 1, aseg = tid & 1;
    const int t_glob = m0 + arow;
    const float2 rs = stt[t_glob];
    float4 pa[4];

    auto ldgA = [&](int ch) {
        const float* src = sc + (long long)t_glob * TT + ch * 32 + aseg * 16;
        pa[0] = *(const float4*)(src + 0);
        pa[1] = *(const float4*)(src + 4);
        pa[2] = *(const float4*)(src + 8);
        pa[3] = *(const float4*)(src + 12);
    };
    auto stsA = [&](int ch) {
        char* stg = smem + (size_t)(ch % 3) * W_STG;
        const int sb0 = ch * 32 + aseg * 16;
        uint32_t hi[8], lo[8];
#pragma unroll
        for (int q = 0; q < 4; q++) {
            const float vv[4] = { pa[q].x, pa[q].y, pa[q].z, pa[q].w };
            float w[4];
#pragma unroll
            for (int e = 0; e < 4; e++) {
                const int s = sb0 + q * 4 + e;
                w[e] = (s < t_glob) ? __expf(vv[e] - rs.x) * rs.y : 0.0f;
            }
#pragma unroll
            for (int e = 0; e < 4; e += 2) {
                const bf16 h0 = __float2bfloat16(w[e]);
                const bf16 h1 = __float2bfloat16(w[e + 1]);
                const bf16 l0 = __float2bfloat16(w[e] - __bfloat162float(h0));
                const bf16 l1 = __float2bfloat16(w[e + 1] - __bfloat162float(h1));
                __nv_bfloat162 ph = __halves2bfloat162(h0, h1);
                __nv_bfloat162 pl = __halves2bfloat162(l0, l1);
                hi[q * 2 + e / 2] = *(uint32_t*)&ph;
                lo[q * 2 + e / 2] = *(uint32_t*)&pl;
            }
        }
        const uint32_t o0 = swz(arow, 2 * aseg);
        const uint32_t o1 = swz(arow, 2 * aseg + 1);
        *(uint4*)(stg + W_AHI + o0) = *(uint4*)(hi + 0);
        *(uint4*)(stg + W_AHI + o1) = *(uint4*)(hi + 4);
        *(uint4*)(stg + W_ALO + o0) = *(uint4*)(lo + 0);
        *(uint4*)(stg + W_ALO + o1) = *(uint4*)(lo + 4);
    };
    auto issueB = [&](int ch) {
        const uint32_t st = sbase + (uint32_t)(ch % 3) * W_STG;
        const long long k0 = (long long)ch * 32;
#pragma unroll
        for (int r = 0; r < 2; r++) {
            const int idx = tid + r * 256;
            const int brow = idx >> 4, bseg = idx & 15;
            const long long go = (k0 + brow) * CC + n0 + bseg * 8;
            const uint32_t so = (uint32_t)(brow * 272 + bseg * 16);
            cp16(st + W_BHI + so, bhi + go);
            cp16(st + W_BLO + so, blo + go);
        }
    };

    float acc[4][4][4];
#pragma unroll
    for (int a = 0; a < 4; a++)
#pragma unroll
        for (int b = 0; b < 4; b++)
#pragma unroll
            for (int c = 0; c < 4; c++) acc[a][b][c] = 0.f;

    ldgA(0);
#pragma unroll
    for (int s = 0; s < 2; s++) {
        if (s < nc) issueB(s);
        asm volatile("cp.async.commit_group;" ::: "memory");
    }

    for (int ch = 0; ch < nc; ch++) {
        asm volatile("cp.async.wait_group 1;" ::: "memory");
        stsA(ch);
        __syncthreads();
        if (ch + 1 < nc) ldgA(ch + 1);
        if (ch + 2 < nc) issueB(ch + 2);
        asm volatile("cp.async.commit_group;" ::: "memory");

        const uint32_t st = sbase + (uint32_t)(ch % 3) * W_STG;

#pragma unroll
        for (int ks = 0; ks < 2; ks++) {
            uint32_t ah[4][4], al[4][4], bh[4][2], bl[4][2];
#pragma unroll
            for (int mt = 0; mt < 4; mt++) {
                const uint32_t ao = swz(arow_base + mt * 16, achunk0 + ks * 2);
                ldsm4(st + W_AHI + ao, ah[mt][0], ah[mt][1], ah[mt][2], ah[mt][3]);
                ldsm4(st + W_ALO + ao, al[mt][0], al[mt][1], al[mt][2], al[mt][3]);
            }
#pragma unroll
            for (int j = 0; j < 2; j++) {
                uint32_t r0, r1, r2, r3;
                ldsm4t(st + W_BHI + bLaneT + ks * (16 * 272) + j * 32, r0, r1, r2, r3);
                bh[2 * j][0] = r0; bh[2 * j][1] = r1; bh[2 * j + 1][0] = r2; bh[2 * j + 1][1] = r3;
                ldsm4t(st + W_BLO + bLaneT + ks * (16 * 272) + j * 32, r0, r1, r2, r3);
                bl[2 * j][0] = r0; bl[2 * j][1] = r1; bl[2 * j + 1][0] = r2; bl[2 * j + 1][1] = r3;
            }
#pragma unroll
            for (int mt = 0; mt < 4; mt++)
#pragma unroll
                for (int nt = 0; nt < 4; nt++) mma_bf16(acc[mt][nt], ah[mt], bh[nt]);
#pragma unroll
            for (int mt = 0; mt < 4; mt++)
#pragma unroll
                for (int nt = 0; nt < 4; nt++) mma_bf16(acc[mt][nt], ah[mt], bl[nt]);
#pragma unroll
            for (int mt = 0; mt < 4; mt++)
#pragma unroll
                for (int nt = 0; nt < 4; nt++) mma_bf16(acc[mt][nt], al[mt], bh[nt]);
        }
    }

    const int rr = lane >> 2, cb = (lane & 3) * 2;
#pragma unroll
    for (int mt = 0; mt < 4; mt++) {
#pragma unroll
        for (int nt = 0; nt < 4; nt++) {
            const int row = m0 + wm * 64 + mt * 16 + rr;
            const int col = n0 + wn * 32 + nt * 8 + cb;
            *(float2*)(out + (long long)row * CC + col) =
                make_float2(-acc[mt][nt][0], -acc[mt][nt][1]);
            *(float2*)(out + (long long)(row + 8) * CC + col) =
                make_float2(-acc[mt][nt][2], -acc[mt][nt][3]);
        }
    }
}

// ===========================================================================
// fp32 -> bf16 hi/lo split
// ===========================================================================
__global__ __launch_bounds__(256) void split_bf16(
    const float* __restrict__ src, bf16* __restrict__ hi, bf16* __restrict__ lo, long long n)
{
    for (long long idx = (long long)blockIdx.x * 256 + threadIdx.x; idx < n;
         idx += (long long)gridDim.x * 256) {
        const float x = src[idx];
        const bf16 h = __float2bfloat16(x);
        hi[idx] = h;
        lo[idx] = __float2bfloat16(x - __bfloat162float(h));
    }
}

// ===========================================================================
// Row stats (vectorized): m = max_{s<t}, inv = 1/sum exp(score-m)
// ===========================================================================
__global__ __launch_bounds__(256) void row_stats(
    const float* __restrict__ sc, float2* __restrict__ stats)
{
    const long long row = blockIdx.x;
    const int t = (int)(row % TT);
    const float* p = sc + row * TT;
    const float4* p4 = (const float4*)p;
    const int n4 = t >> 2;
    const int tid = threadIdx.x;

    __shared__ float red[8];

    float m = -3.0e38f;
    for (int q = tid; q < n4; q += 256) {
        const float4 v = p4[q];
        m = fmaxf(m, fmaxf(fmaxf(v.x, v.y), fmaxf(v.z, v.w)));
    }
    for (int s = (n4 << 2) + tid; s < t; s += 256) m = fmaxf(m, p[s]);
#pragma unroll
    for (int o = 16; o; o >>= 1) m = fmaxf(m, __shfl_xor_sync(0xffffffffu, m, o));
    if ((tid & 31) == 0) red[tid >> 5] = m;
    __syncthreads();
    m = red[0];
#pragma unroll
    for (int w = 1; w < 8; w++) m = fmaxf(m, red[w]);
    __syncthreads();

    float sum = 0.0f;
    for (int q = tid; q < n4; q += 256) {
        const float4 v = p4[q];
        sum += __expf(v.x - m) + __expf(v.y - m) + __expf(v.z - m) + __expf(v.w - m);
    }
    for (int s = (n4 << 2) + tid; s < t; s += 256) sum += __expf(p[s] - m);
#pragma unroll
    for (int o = 16; o; o >>= 1) sum += __shfl_xor_sync(0xffffffffu, sum, o);
    if ((tid & 31) == 0) red[tid >> 5] = sum;
    __syncthreads();

    if (tid == 0) {
        sum = red[0] + red[1] + red[2] + red[3] + red[4] + red[5] + red[6] + red[7];
        stats[row] = make_float2(m, (t > 0) ? (1.0f / sum) : 0.0f);
    }
}

// ===========================================================================
extern "C" void kernel_launch(void* const* d_in, const int* in_sizes, int n_in,
                              void* d_out, int out_size)
{
    const float* x = (const float*)d_in[0];
    const float* W = (const float*)d_in[1];
    float* out = (float*)d_out;

    bf16 *xhi, *xlo, *whi, *wlo, *xHhi, *xHlo;
    float* sc; float2* stats;
    cudaGetSymbolAddress((void**)&xhi,   g_xhi);
    cudaGetSymbolAddress((void**)&xlo,   g_xlo);
    cudaGetSymbolAddress((void**)&whi,   g_whi);
    cudaGetSymbolAddress((void**)&wlo,   g_wlo);
    cudaGetSymbolAddress((void**)&xHhi,  g_xHhi);
    cudaGetSymbolAddress((void**)&xHlo,  g_xHlo);
    cudaGetSymbolAddress((void**)&sc,    g_sc);
    cudaGetSymbolAddress((void**)&stats, g_stats);

    cudaFuncSetAttribute(gemm_bf3<false, 2>,
                         cudaFuncAttributeMaxDynamicSharedMemorySize, SMEM_TOTAL);
    cudaFuncSetAttribute(gemm_bf3<true, 0>,
                         cudaFuncAttributeMaxDynamicSharedMemorySize, SMEM_TOTAL);
    cudaFuncSetAttribute(gemm_wei,
                         cudaFuncAttributeMaxDynamicSharedMemorySize, W_SMEM);

    split_bf16<<<8192, 256>>>(x, xhi, xlo, (long long)BB * TT * CC);
    split_bf16<<<2048, 256>>>(W, whi, wlo, (long long)CC * CC);

    // K1: xH = x @ W^T  -> bf16 hi/lo
    gemm_bf3<false, 2><<<dim3(CC / 128, (BB * TT) / 128, 1), 256, SMEM_TOTAL>>>(
        xhi, xlo, whi, wlo, nullptr, xHhi, xHlo,
        CC, CC, CC, CC, 0, 0, 0);

    // K2: scores(fp32) = x @ xH^T per batch, causal tiles only
    gemm_bf3<true, 0><<<dim3(TT / 128, TT / 128, BB), 256, SMEM_TOTAL>>>(
        xhi, xlo, xHhi, xHlo, sc, nullptr, nullptr,
        CC, CC, TT, CC,
        (long long)TT * CC, (long long)TT * CC, (long long)TT * TT);

    // K3: row stats
    row_stats<<<BB * TT, 256>>>(sc, stats);

    // K4: out = -(wei @ xH), wei on the fly, K clamped
    gemm_wei<<<dim3(CC / 128, TT / 128, BB), 256, W_SMEM>>>(
        sc, stats, xHhi, xHlo, out);
}